// round 6
// baseline (speedup 1.0000x reference)
#include <cuda_runtime.h>
#include <cuda_fp16.h>
#include <cstdint>

#define B_ 8
#define D_ 128
#define N_ 2048
#define BM 64
#define BN 64
#define NITER (N_ / BN)

__device__ __align__(16) __half g_Qh[B_ * D_ * N_];  // [b][d][n] fp16 (native layout)
__device__ __align__(16) __half g_Kh[B_ * D_ * N_];  // [b][d][m]
__device__ __align__(16) __half g_Vh[B_ * D_ * N_];  // [b][v][n]

__device__ __forceinline__ uint32_t s2u(const void* p) {
    uint32_t a;
    asm("{ .reg .u64 t; cvta.to.shared.u64 t, %1; cvt.u32.u64 %0, t; }" : "=r"(a) : "l"(p));
    return a;
}

#define CPA16(dst, src) \
    asm volatile("cp.async.cg.shared.global [%0], [%1], 16;" :: "r"(dst), "l"(src))
#define CPA_COMMIT() asm volatile("cp.async.commit_group;" ::: "memory")
#define CPA_WAIT0()  asm volatile("cp.async.wait_group 0;" ::: "memory")

__device__ __forceinline__ void ldmx4(uint32_t* r, uint32_t addr) {
    asm volatile("ldmatrix.sync.aligned.m8n8.x4.shared.b16 {%0,%1,%2,%3}, [%4];"
        : "=r"(r[0]), "=r"(r[1]), "=r"(r[2]), "=r"(r[3]) : "r"(addr));
}
__device__ __forceinline__ void ldmx4t(uint32_t* r, uint32_t addr) {
    asm volatile("ldmatrix.sync.aligned.m8n8.x4.trans.shared.b16 {%0,%1,%2,%3}, [%4];"
        : "=r"(r[0]), "=r"(r[1]), "=r"(r[2]), "=r"(r[3]) : "r"(addr));
}
__device__ __forceinline__ void mma16816(float* d, const uint32_t* a, const uint32_t* b) {
    asm volatile("mma.sync.aligned.m16n8k16.row.col.f32.f16.f16.f32 "
        "{%0,%1,%2,%3}, {%4,%5,%6,%7}, {%8,%9}, {%0,%1,%2,%3};"
        : "+f"(d[0]), "+f"(d[1]), "+f"(d[2]), "+f"(d[3])
        : "r"(a[0]), "r"(a[1]), "r"(a[2]), "r"(a[3]), "r"(b[0]), "r"(b[1]));
}

// sigmoid(x/sqrt(128)) = 0.5*tanh(x/(2*sqrt(128))) + 0.5  (single MUFU)
__device__ __forceinline__ float sigf(float x) {
    const float c = 0.5f * 0.08838834764831845f;
    float t;
    asm("tanh.approx.f32 %0, %1;" : "=f"(t) : "f"(x * c));
    return fmaf(t, 0.5f, 0.5f);
}
__device__ __forceinline__ uint32_t packh2(float a, float b) {
    uint32_t r;
    asm("cvt.rn.f16x2.f32 %0, %1, %2;" : "=r"(r) : "f"(b), "f"(a));
    return r;
}

// smem: K [d=128][m=64] 16KB @0, Q[buf] [d=128][n=64] 16KB @16K, V[buf] 16KB @48K
#define SM_K 0
#define SM_Q 16384
#define SM_V 49152
#define SMEM_TOTAL 81920

__global__ __launch_bounds__(128, 2)
void sigattn_hmma(float* __restrict__ O) {
    extern __shared__ char sm[];
    const uint32_t sb = s2u(sm);
    const int tid = threadIdx.x, w = tid >> 5, lane = tid & 31;
    const int b = blockIdx.y, m0 = blockIdx.x * BM;
    const int g = lane >> 3, sx = lane & 7;

    auto loadQV = [&](int it, int buf) {
        const int n0 = it * BN;
        const uint32_t qd = sb + SM_Q + buf * 16384;
        const uint32_t vd = sb + SM_V + buf * 16384;
#pragma unroll
        for (int r = 0; r < 8; r++) {
            int i = tid + r * 128;
            int d = i >> 3, c = i & 7;                 // 128 rows x 8 chunks(16B)
            uint32_t off = (uint32_t)(d * 128 + ((c ^ (d & 7)) << 4));
            CPA16(qd + off, (const char*)g_Qh + ((size_t)(b * D_ + d) * N_ + n0 + c * 8) * 2);
            CPA16(vd + off, (const char*)g_Vh + ((size_t)(b * D_ + d) * N_ + n0 + c * 8) * 2);
        }
    };

    // prologue: K tile [d][m0..m0+63] + (Q,V)(0)
#pragma unroll
    for (int r = 0; r < 8; r++) {
        int i = tid + r * 128;
        int d = i >> 3, c = i & 7;                     // 128 rows x 8 chunks
        CPA16(sb + SM_K + d * 128 + ((c ^ (d & 7)) << 4),
              (const char*)g_Kh + ((size_t)(b * D_ + d) * N_ + m0 + c * 8) * 2);
    }
    loadQV(0, 0);
    CPA_COMMIT();
    CPA_WAIT0();
    __syncthreads();

    // ---- K frags (A m16k16, m-block = w in 0..3) via ldmatrix.trans from [d][m] ----
    uint32_t kf[8][4];
    {
        const int drow = (g >> 1) * 8 + sx;            // d offset within 16-chunk
        const uint32_t coff = (uint32_t)((((2 * w + (g & 1)) ^ sx) & 7) << 4);
#pragma unroll
        for (int kc = 0; kc < 8; kc++)
            ldmx4t(kf[kc], sb + SM_K + (uint32_t)((kc * 16 + drow) * 128) + coff);
    }

    float ob[16][4];
#pragma unroll
    for (int i = 0; i < 16; i++)
#pragma unroll
        for (int j = 0; j < 4; j++) ob[i][j] = 0.0f;

    const int qrow  = (g & 1) * 8 + sx;                // Q trans-tile d-row offset
    const int qcoff = g >> 1;                          // Q chunk parity
    const int rL    = sx + ((lane >> 4) << 3);         // V ldmatrix row
    const int cp_   = g & 1;                           // V chunk parity

    for (int it = 0; it < NITER; it++) {
        const int buf = it & 1;
        if (it + 1 < NITER) loadQV(it + 1, buf ^ 1);
        CPA_COMMIT();

        // ---- MMA1: S'[16m, 64n] = K . Q^T (Q frags via ldmatrix.trans) ----
        float sc[8][4];
#pragma unroll
        for (int j = 0; j < 8; j++)
#pragma unroll
            for (int q = 0; q < 4; q++) sc[j][q] = 0.0f;

        const uint32_t qbuf = sb + SM_Q + buf * 16384;
#pragma unroll
        for (int kc = 0; kc < 8; kc++) {
            uint32_t qb4[16];
            const uint32_t qr = qbuf + (uint32_t)((kc * 16 + qrow) * 128);
#pragma unroll
            for (int t = 0; t < 4; t++)
                ldmx4t(&qb4[t * 4], qr + (uint32_t)((((2 * t + qcoff) ^ sx) & 7) << 4));
#pragma unroll
            for (int j = 0; j < 8; j++)
                mma16816(sc[j], kf[kc], &qb4[(j >> 1) * 4 + (j & 1) * 2]);
        }

        // ---- sigmoid -> P frags (registers only) ----
        uint32_t p[8][2];
#pragma unroll
        for (int j = 0; j < 8; j++) {
            p[j][0] = packh2(sigf(sc[j][0]), sigf(sc[j][1]));
            p[j][1] = packh2(sigf(sc[j][2]), sigf(sc[j][3]));
        }

        // ---- MMA2: O[16m, 128v] += P . V^T ----
        const uint32_t vbase = sb + SM_V + buf * 16384 + (uint32_t)(rL * 128);
#pragma unroll
        for (int kc = 0; kc < 4; kc++) {
            const uint32_t swz = (uint32_t)((((2 * kc + cp_) ^ sx) & 7) << 4);
            uint32_t a[4] = { p[2 * kc][0], p[2 * kc][1], p[2 * kc + 1][0], p[2 * kc + 1][1] };
#pragma unroll
            for (int j = 0; j < 8; j++) {
                uint32_t vb[4];
                ldmx4(vb, vbase + (uint32_t)(j * 2048) + swz);
                mma16816(ob[2 * j],     a, &vb[0]);
                mma16816(ob[2 * j + 1], a, &vb[2]);
            }
        }

        CPA_WAIT0();
        __syncthreads();
    }

    // ---- epilogue: O'[m,v] -> O[b][v][m0+m] ----
    float* Ob = O + (size_t)b * D_ * N_ + m0;
    const int r  = w * 16 + (lane >> 2);
    const int c0 = 2 * (lane & 3);
#pragma unroll
    for (int i = 0; i < 16; i++) {
        const int v = 8 * i + c0;
        Ob[(size_t)v * N_ + r]           = ob[i][0];
        Ob[(size_t)(v + 1) * N_ + r]     = ob[i][1];
        Ob[(size_t)v * N_ + r + 8]       = ob[i][2];
        Ob[(size_t)(v + 1) * N_ + r + 8] = ob[i][3];
    }
}

// ---- preprocess: pure fp32 -> fp16 cast, native layouts ----
__global__ void prep_cast(const float* __restrict__ Q, const float* __restrict__ K,
                          const float* __restrict__ V) {
    int i = blockIdx.x * 256 + threadIdx.x;
    const float* src = (blockIdx.y == 0) ? Q : (blockIdx.y == 1) ? K : V;
    __half* dst = (blockIdx.y == 0) ? g_Qh : (blockIdx.y == 1) ? g_Kh : g_Vh;
    float4 v = ((const float4*)src)[i];
    __half2* o = (__half2*)dst;
    o[2 * i]     = __floats2half2_rn(v.x, v.y);
    o[2 * i + 1] = __floats2half2_rn(v.z, v.w);
}

extern "C" void kernel_launch(void* const* d_in, const int* in_sizes, int n_in,
                              void* d_out, int out_size) {
    const float* Q = (const float*)d_in[0];
    const float* K = (const float*)d_in[1];
    const float* V = (const float*)d_in[2];
    float* O = (float*)d_out;

    prep_cast<<<dim3((B_ * D_ * N_ / 4) / 256, 3), 256>>>(Q, K, V);

    cudaFuncSetAttribute(sigattn_hmma, cudaFuncAttributeMaxDynamicSharedMemorySize, SMEM_TOTAL);
    sigattn_hmma<<<dim3(N_ / BM, B_), 128, SMEM_TOTAL>>>(O);
}

// round 7
// speedup vs baseline: 1.0052x; 1.0052x over previous
#include <cuda_runtime.h>
#include <cuda_fp16.h>
#include <cstdint>

#define B_ 8
#define D_ 128
#define N_ 2048
#define BM 128
#define BN 128
#define NITER (N_ / BN)

__device__ __align__(16) __half g_Qh[B_ * D_ * N_];  // [b][d][n] fp16 (native layout)
__device__ __align__(16) __half g_Kh[B_ * D_ * N_];  // [b][d][m]
__device__ __align__(16) __half g_Vh[B_ * D_ * N_];  // [b][v][n]

__device__ __forceinline__ uint32_t s2u(const void* p) {
    uint32_t a;
    asm("{ .reg .u64 t; cvta.to.shared.u64 t, %1; cvt.u32.u64 %0, t; }" : "=r"(a) : "l"(p));
    return a;
}

#define CPA16(dst, src) \
    asm volatile("cp.async.cg.shared.global [%0], [%1], 16;" :: "r"(dst), "l"(src))
#define CPA_COMMIT() asm volatile("cp.async.commit_group;" ::: "memory")
#define CPA_WAIT0()  asm volatile("cp.async.wait_group 0;" ::: "memory")

__device__ __forceinline__ void ldmx4(uint32_t* r, uint32_t addr) {
    asm volatile("ldmatrix.sync.aligned.m8n8.x4.shared.b16 {%0,%1,%2,%3}, [%4];"
        : "=r"(r[0]), "=r"(r[1]), "=r"(r[2]), "=r"(r[3]) : "r"(addr));
}
__device__ __forceinline__ void ldmx4t(uint32_t* r, uint32_t addr) {
    asm volatile("ldmatrix.sync.aligned.m8n8.x4.trans.shared.b16 {%0,%1,%2,%3}, [%4];"
        : "=r"(r[0]), "=r"(r[1]), "=r"(r[2]), "=r"(r[3]) : "r"(addr));
}
__device__ __forceinline__ void mma16816(float* d, const uint32_t* a, const uint32_t* b) {
    asm volatile("mma.sync.aligned.m16n8k16.row.col.f32.f16.f16.f32 "
        "{%0,%1,%2,%3}, {%4,%5,%6,%7}, {%8,%9}, {%0,%1,%2,%3};"
        : "+f"(d[0]), "+f"(d[1]), "+f"(d[2]), "+f"(d[3])
        : "r"(a[0]), "r"(a[1]), "r"(a[2]), "r"(a[3]), "r"(b[0]), "r"(b[1]));
}

// sigmoid(x/sqrt(128)) = 0.5*tanh(x/(2*sqrt(128))) + 0.5  (single MUFU)
__device__ __forceinline__ float sigf(float x) {
    const float c = 0.5f * 0.08838834764831845f;
    float t;
    asm("tanh.approx.f32 %0, %1;" : "=f"(t) : "f"(x * c));
    return fmaf(t, 0.5f, 0.5f);
}
__device__ __forceinline__ uint32_t packh2(float a, float b) {
    uint32_t r;
    asm("cvt.rn.f16x2.f32 %0, %1, %2;" : "=r"(r) : "f"(b), "f"(a));
    return r;
}

// smem: K [d=128][m=128] 32KB @0, Q[buf] [d=128][n=128] 32KB @32K, V[buf] 32KB @96K
#define SM_K 0
#define SM_Q 32768
#define SM_V 98304
#define SMEM_TOTAL 163840

__global__ __launch_bounds__(256, 1)
void sigattn_hmma(float* __restrict__ O) {
    extern __shared__ char sm[];
    const uint32_t sb = s2u(sm);
    const int tid = threadIdx.x, w = tid >> 5, lane = tid & 31;
    const int b = blockIdx.y, m0 = blockIdx.x * BM;
    const int g = lane >> 3, sx = lane & 7;

    auto loadQV = [&](int it, int buf) {
        const int n0 = it * BN;
        const uint32_t qd = sb + SM_Q + buf * 32768;
        const uint32_t vd = sb + SM_V + buf * 32768;
#pragma unroll
        for (int r = 0; r < 8; r++) {
            int i = tid + r * 256;
            int d = i >> 4, c = i & 15;                // 128 rows x 16 chunks(16B)
            uint32_t off = (uint32_t)(d * 256 + ((c ^ (d & 7)) << 4));
            CPA16(qd + off, (const char*)g_Qh + ((size_t)(b * D_ + d) * N_ + n0 + c * 8) * 2);
            CPA16(vd + off, (const char*)g_Vh + ((size_t)(b * D_ + d) * N_ + n0 + c * 8) * 2);
        }
    };

    // prologue: K tile [d][m0..m0+127] + (Q,V)(0)
#pragma unroll
    for (int r = 0; r < 8; r++) {
        int i = tid + r * 256;
        int d = i >> 4, c = i & 15;
        CPA16(sb + SM_K + d * 256 + ((c ^ (d & 7)) << 4),
              (const char*)g_Kh + ((size_t)(b * D_ + d) * N_ + m0 + c * 8) * 2);
    }
    loadQV(0, 0);
    CPA_COMMIT();
    CPA_WAIT0();
    __syncthreads();

    // ---- K frags (A m16k16, m-block = w) via ldmatrix.trans from [d][m] ----
    uint32_t kf[8][4];
    {
        const int drow = (g >> 1) * 8 + sx;
        const uint32_t coff = (uint32_t)((((2 * w + (g & 1)) ^ sx) & 15) << 4);
#pragma unroll
        for (int kc = 0; kc < 8; kc++)
            ldmx4t(kf[kc], sb + SM_K + (uint32_t)((kc * 16 + drow) * 256) + coff);
    }

    float ob[16][4];
#pragma unroll
    for (int i = 0; i < 16; i++)
#pragma unroll
        for (int j = 0; j < 4; j++) ob[i][j] = 0.0f;

    const int qrow  = (g & 1) * 8 + sx;                // Q trans-tile d-row offset
    const int qcoff = g >> 1;                          // Q chunk parity
    const int rL    = sx + ((lane >> 4) << 3);         // V ldmatrix row
    const int cp_   = g & 1;                           // V chunk parity

    for (int it = 0; it < NITER; it++) {
        const int buf = it & 1;
        if (it + 1 < NITER) { loadQV(it + 1, buf ^ 1); CPA_COMMIT(); }

        const uint32_t qbuf = sb + SM_Q + buf * 32768;
        const uint32_t vbuf = sb + SM_V + buf * 32768;

        // MMA1 on a 32-n chunk ci (n = ci*32 .. ci*32+31)
        auto do_mma1 = [&](int ci, float (&sc)[4][4]) {
#pragma unroll
            for (int jl = 0; jl < 4; jl++)
#pragma unroll
                for (int q = 0; q < 4; q++) sc[jl][q] = 0.0f;
#pragma unroll
            for (int kc = 0; kc < 8; kc++) {
                uint32_t qb8[8];
                const uint32_t qr = qbuf + (uint32_t)((kc * 16 + qrow) * 256);
                ldmx4t(&qb8[0], qr + (uint32_t)((((4 * ci + qcoff)     ^ sx) & 15) << 4));
                ldmx4t(&qb8[4], qr + (uint32_t)((((4 * ci + 2 + qcoff) ^ sx) & 15) << 4));
                mma16816(sc[0], kf[kc], &qb8[0]);
                mma16816(sc[1], kf[kc], &qb8[2]);
                mma16816(sc[2], kf[kc], &qb8[4]);
                mma16816(sc[3], kf[kc], &qb8[6]);
            }
        };
        // MMA2 on chunk ci with P frags
        auto do_mma2 = [&](int ci, uint32_t (&p)[4][2]) {
#pragma unroll
            for (int kcl = 0; kcl < 2; kcl++) {
                const int cv = 4 * ci + 2 * kcl + cp_;
                const uint32_t swz = (uint32_t)(((cv ^ sx) & 15) << 4);
                uint32_t a[4] = { p[2 * kcl][0], p[2 * kcl][1],
                                  p[2 * kcl + 1][0], p[2 * kcl + 1][1] };
#pragma unroll
                for (int j = 0; j < 8; j++) {
                    uint32_t vb[4];
                    ldmx4(vb, vbuf + (uint32_t)(rL * 256 + j * 4096) + swz);
                    mma16816(ob[2 * j],     a, &vb[0]);
                    mma16816(ob[2 * j + 1], a, &vb[2]);
                }
            }
        };

        // pipelined chunks: MMA1(c+1) overlaps sig(c)+MMA2(c)
        float sc[2][4][4];
        do_mma1(0, sc[0]);
#pragma unroll
        for (int ci = 0; ci < 4; ci++) {
            if (ci < 3) do_mma1(ci + 1, sc[(ci + 1) & 1]);
            uint32_t p[4][2];
            float (&s)[4][4] = sc[ci & 1];
#pragma unroll
            for (int jl = 0; jl < 4; jl++) {
                p[jl][0] = packh2(sigf(s[jl][0]), sigf(s[jl][1]));
                p[jl][1] = packh2(sigf(s[jl][2]), sigf(s[jl][3]));
            }
            do_mma2(ci, p);
        }

        CPA_WAIT0();
        __syncthreads();
    }

    // ---- epilogue: O'[m,v] -> O[b][v][m0+m] ----
    float* Ob = O + (size_t)b * D_ * N_ + m0;
    const int r  = w * 16 + (lane >> 2);
    const int c0 = 2 * (lane & 3);
#pragma unroll
    for (int i = 0; i < 16; i++) {
        const int v = 8 * i + c0;
        Ob[(size_t)v * N_ + r]           = ob[i][0];
        Ob[(size_t)(v + 1) * N_ + r]     = ob[i][1];
        Ob[(size_t)v * N_ + r + 8]       = ob[i][2];
        Ob[(size_t)(v + 1) * N_ + r + 8] = ob[i][3];
    }
}

// ---- preprocess: pure fp32 -> fp16 cast, native layouts ----
__global__ void prep_cast(const float* __restrict__ Q, const float* __restrict__ K,
                          const float* __restrict__ V) {
    int i = blockIdx.x * 256 + threadIdx.x;
    const float* src = (blockIdx.y == 0) ? Q : (blockIdx.y == 1) ? K : V;
    __half* dst = (blockIdx.y == 0) ? g_Qh : (blockIdx.y == 1) ? g_Kh : g_Vh;
    float4 v = ((const float4*)src)[i];
    __half2* o = (__half2*)dst;
    o[2 * i]     = __floats2half2_rn(v.x, v.y);
    o[2 * i + 1] = __floats2half2_rn(v.z, v.w);
}

extern "C" void kernel_launch(void* const* d_in, const int* in_sizes, int n_in,
                              void* d_out, int out_size) {
    const float* Q = (const float*)d_in[0];
    const float* K = (const float*)d_in[1];
    const float* V = (const float*)d_in[2];
    float* O = (float*)d_out;

    prep_cast<<<dim3((B_ * D_ * N_ / 4) / 256, 3), 256>>>(Q, K, V);

    cudaFuncSetAttribute(sigattn_hmma, cudaFuncAttributeMaxDynamicSharedMemorySize, SMEM_TOTAL);
    sigattn_hmma<<<dim3(N_ / BM, B_), 256, SMEM_TOTAL>>>(O);
}